// round 14
// baseline (speedup 1.0000x reference)
#include <cuda_runtime.h>
#include <cuda_bf16.h>
#include <cstdint>

#define Bn 256
#define Tn 512
#define Fn 128
#define Hn 256
#define BT (Bn*Tn)
#define BH (Bn*Hn)
#define SROW 72
#define SROWK 264   // LSTM smem row stride (256 k + 8 pad)

// weight split buffer offsets (elements)
#define W_SA   0
#define W_IN   16384
#define W_IH0  49152
#define W_IH1  311296
#define W_TAH  573440
#define W_TA   606208
#define W_TOT  622592

// ---------------- scratch (device globals) ----------------
__device__ float g_bufF1[(size_t)BT * Fn];
__device__ float g_bufF2[(size_t)BT * Fn];
__device__ float g_bufG [(size_t)BT * 4 * Hn];
__device__ float g_ctxbuf[Bn * Fn];
__device__ __nv_bfloat16 g_a16h[(size_t)BT * Hn];   // activation pair buffer A1
__device__ __nv_bfloat16 g_a16l[(size_t)BT * Hn];
__device__ __nv_bfloat16 g_b16h[(size_t)BT * Hn];   // activation pair buffer A2
__device__ __nv_bfloat16 g_b16l[(size_t)BT * Hn];
__device__ __nv_bfloat16 g_w16h[W_TOT];             // all weights hi
__device__ __nv_bfloat16 g_w16l[W_TOT];             // all weights lo
__device__ __nv_bfloat16 g_h16h[2 * BH];            // ping-pong h (bf16 hi)
__device__ __nv_bfloat16 g_h16l[2 * BH];            // ping-pong h (bf16 lo)

// ---------------- BatchNorm (eval) + bf16 pair emit ----------------
__global__ void bn_kernel(const float4* __restrict__ x, const float4* __restrict__ g,
                          const float4* __restrict__ bt, const float4* __restrict__ mn,
                          const float4* __restrict__ vr, float4* __restrict__ out,
                          __nv_bfloat162* __restrict__ oh, __nv_bfloat162* __restrict__ ol)
{
    int i = blockIdx.x * 256 + threadIdx.x;
    int fi = i & 31;
    float4 xv = x[i];
    float4 gv = g[fi];
    float4 bv = bt[fi];
    float4 mv = mn[fi];
    float4 vv = vr[fi];
    float4 r;
    r.x = (xv.x - mv.x) * rsqrtf(vv.x + 1e-5f) * gv.x + bv.x;
    r.y = (xv.y - mv.y) * rsqrtf(vv.y + 1e-5f) * gv.y + bv.y;
    r.z = (xv.z - mv.z) * rsqrtf(vv.z + 1e-5f) * gv.z + bv.z;
    r.w = (xv.w - mv.w) * rsqrtf(vv.w + 1e-5f) * gv.w + bv.w;
    out[i] = r;
    __nv_bfloat162 h0 = __floats2bfloat162_rn(r.x, r.y);
    __nv_bfloat162 h1 = __floats2bfloat162_rn(r.z, r.w);
    float lx = r.x - __bfloat162float(__low2bfloat16(h0));
    float ly = r.y - __bfloat162float(__high2bfloat16(h0));
    float lz = r.z - __bfloat162float(__low2bfloat16(h1));
    float lw = r.w - __bfloat162float(__high2bfloat16(h1));
    oh[2 * i]     = h0;
    oh[2 * i + 1] = h1;
    ol[2 * i]     = __floats2bfloat162_rn(lx, ly);
    ol[2 * i + 1] = __floats2bfloat162_rn(lz, lw);
}

// ---------------- fp32 -> bf16 hi/lo split (weights) ----------------
__global__ void split_kernel(const float4* __restrict__ x,
                             __nv_bfloat162* __restrict__ hh,
                             __nv_bfloat162* __restrict__ ll)
{
    int i = blockIdx.x * 256 + threadIdx.x;
    float4 v = x[i];
    __nv_bfloat162 h0 = __floats2bfloat162_rn(v.x, v.y);
    __nv_bfloat162 h1 = __floats2bfloat162_rn(v.z, v.w);
    float lx = v.x - __bfloat162float(__low2bfloat16(h0));
    float ly = v.y - __bfloat162float(__high2bfloat16(h0));
    float lz = v.z - __bfloat162float(__low2bfloat16(h1));
    float lw = v.w - __bfloat162float(__high2bfloat16(h1));
    hh[2 * i]     = h0;
    hh[2 * i + 1] = h1;
    ll[2 * i]     = __floats2bfloat162_rn(lx, ly);
    ll[2 * i + 1] = __floats2bfloat162_rn(lz, lw);
}

// ---------------- tensor-core helpers ----------------
__device__ __forceinline__ void ldsm_x4(uint32_t* r, uint32_t saddr)
{
    asm volatile("ldmatrix.sync.aligned.m8n8.x4.shared.b16 {%0,%1,%2,%3}, [%4];"
                 : "=r"(r[0]), "=r"(r[1]), "=r"(r[2]), "=r"(r[3]) : "r"(saddr));
}

__device__ __forceinline__ void ldsm_x2(uint32_t* r, uint32_t saddr)
{
    asm volatile("ldmatrix.sync.aligned.m8n8.x2.shared.b16 {%0,%1}, [%2];"
                 : "=r"(r[0]), "=r"(r[1]) : "r"(saddr));
}

__device__ __forceinline__ void mma_bf16(float* d, const uint32_t* a, const uint32_t* b)
{
    asm volatile("mma.sync.aligned.m16n8k16.row.col.f32.bf16.bf16.f32 "
                 "{%0,%1,%2,%3}, {%4,%5,%6,%7}, {%8,%9}, {%0,%1,%2,%3};"
                 : "+f"(d[0]), "+f"(d[1]), "+f"(d[2]), "+f"(d[3])
                 : "r"(a[0]), "r"(a[1]), "r"(a[2]), "r"(a[3]), "r"(b[0]), "r"(b[1]));
}

// ---------------- unified bf16-split tensor GEMM ----------------
__global__ __launch_bounds__(256) void gemm_bf16_kernel(
    const __nv_bfloat16* __restrict__ Ahg, const __nv_bfloat16* __restrict__ Alg,
    const __nv_bfloat16* __restrict__ Whg, const __nv_bfloat16* __restrict__ Wlg,
    const float* __restrict__ b1, const float* __restrict__ b2,
    float* __restrict__ Cf, __nv_bfloat16* __restrict__ Chi, __nv_bfloat16* __restrict__ Clo,
    int N, int K, int epi)
{
    extern __shared__ char dynsmem[];
    __nv_bfloat16* sAh = (__nv_bfloat16*)dynsmem;
    __nv_bfloat16* sAl = sAh + 128 * SROW;
    __nv_bfloat16* sWh = sAl + 128 * SROW;
    __nv_bfloat16* sWl = sWh + 128 * SROW;

    const int m0 = blockIdx.y << 7;
    const int n0 = blockIdx.x << 7;
    const int tid = (int)threadIdx.x;
    const int wid = tid >> 5;
    const int lane = tid & 31;
    const int wm0 = (wid >> 2) << 6;
    const int wn0 = (wid & 3) << 5;

    const int arow = (lane & 7) + (((lane >> 3) & 1) << 3);
    const int acol = (lane >> 4) << 3;
    const int brow = (lane & 7) + ((lane >> 4) << 3);
    const int bcol = ((lane >> 3) & 1) << 3;

    const uint32_t sAh0 = (uint32_t)__cvta_generic_to_shared(sAh) + (uint32_t)(((wm0 + arow) * SROW + acol) * 2);
    const uint32_t sAl0 = (uint32_t)__cvta_generic_to_shared(sAl) + (uint32_t)(((wm0 + arow) * SROW + acol) * 2);
    const uint32_t sWh0 = (uint32_t)__cvta_generic_to_shared(sWh) + (uint32_t)(((wn0 + brow) * SROW + bcol) * 2);
    const uint32_t sWl0 = (uint32_t)__cvta_generic_to_shared(sWl) + (uint32_t)(((wn0 + brow) * SROW + bcol) * 2);

    float acc[16][4];
#pragma unroll
    for (int i = 0; i < 16; i++) {
#pragma unroll
        for (int j = 0; j < 4; j++) { acc[i][j] = 0.f; }
    }

    const int lr = tid >> 1;
    const int lc = (tid & 1) << 5;
    const int nkc = K >> 6;

    for (int kc = 0; kc < nkc; kc++) {
        const __nv_bfloat16* ag = Ahg + (size_t)(m0 + lr) * K + kc * 64 + lc;
        const __nv_bfloat16* al = Alg + (size_t)(m0 + lr) * K + kc * 64 + lc;
        const __nv_bfloat16* wg = Whg + (size_t)(n0 + lr) * K + kc * 64 + lc;
        const __nv_bfloat16* wl = Wlg + (size_t)(n0 + lr) * K + kc * 64 + lc;
        __nv_bfloat16* dA_h = sAh + lr * SROW + lc;
        __nv_bfloat16* dA_l = sAl + lr * SROW + lc;
        __nv_bfloat16* dW_h = sWh + lr * SROW + lc;
        __nv_bfloat16* dW_l = sWl + lr * SROW + lc;
#pragma unroll
        for (int q = 0; q < 4; q++) {
            ((uint4*)(dA_h + q * 8))[0] = ((const uint4*)(ag + q * 8))[0];
            ((uint4*)(dA_l + q * 8))[0] = ((const uint4*)(al + q * 8))[0];
            ((uint4*)(dW_h + q * 8))[0] = ((const uint4*)(wg + q * 8))[0];
            ((uint4*)(dW_l + q * 8))[0] = ((const uint4*)(wl + q * 8))[0];
        }
        __syncthreads();

#pragma unroll
        for (int ks = 0; ks < 4; ks++) {
            const uint32_t koff = (uint32_t)(ks * 32);
            uint32_t afr[4][4];
            uint32_t bh[4][2];
            uint32_t bl[4][2];
#pragma unroll
            for (int fp = 0; fp < 2; fp++) {
                uint32_t tmp[4];
                ldsm_x4(tmp, sWh0 + (uint32_t)(fp * 16 * SROW * 2) + koff);
                bh[2 * fp][0] = tmp[0];
                bh[2 * fp][1] = tmp[1];
                bh[2 * fp + 1][0] = tmp[2];
                bh[2 * fp + 1][1] = tmp[3];
                ldsm_x4(tmp, sWl0 + (uint32_t)(fp * 16 * SROW * 2) + koff);
                bl[2 * fp][0] = tmp[0];
                bl[2 * fp][1] = tmp[1];
                bl[2 * fp + 1][0] = tmp[2];
                bl[2 * fp + 1][1] = tmp[3];
            }
#pragma unroll
            for (int fm = 0; fm < 4; fm++) {
                ldsm_x4(afr[fm], sAh0 + (uint32_t)(fm * 16 * SROW * 2) + koff);
            }
#pragma unroll
            for (int fm = 0; fm < 4; fm++) {
#pragma unroll
                for (int fn = 0; fn < 4; fn++) {
                    mma_bf16(acc[fm * 4 + fn], afr[fm], bh[fn]);
                    mma_bf16(acc[fm * 4 + fn], afr[fm], bl[fn]);
                }
            }
#pragma unroll
            for (int fm = 0; fm < 4; fm++) {
                ldsm_x4(afr[fm], sAl0 + (uint32_t)(fm * 16 * SROW * 2) + koff);
            }
#pragma unroll
            for (int fm = 0; fm < 4; fm++) {
#pragma unroll
                for (int fn = 0; fn < 4; fn++) {
                    mma_bf16(acc[fm * 4 + fn], afr[fm], bh[fn]);
                }
            }
        }
        __syncthreads();
    }

#pragma unroll
    for (int fm = 0; fm < 4; fm++) {
#pragma unroll
        for (int fn = 0; fn < 4; fn++) {
            float* d = acc[fm * 4 + fn];
            int row = m0 + wm0 + fm * 16 + (lane >> 2);
            int col = n0 + wn0 + fn * 8 + ((lane & 3) << 1);
            float bv0 = b1[col];
            float bv1 = b1[col + 1];
            if (b2 != nullptr) {
                bv0 += b2[col];
                bv1 += b2[col + 1];
            }
            float v00 = d[0] + bv0;
            float v01 = d[1] + bv1;
            float v10 = d[2] + bv0;
            float v11 = d[3] + bv1;
            if (epi == 1) {
                v00 = 1.f / (1.f + expf(-v00));
                v01 = 1.f / (1.f + expf(-v01));
                v10 = 1.f / (1.f + expf(-v10));
                v11 = 1.f / (1.f + expf(-v11));
            } else if (epi == 2) {
                v00 = fmaxf(v00, 0.f);
                v01 = fmaxf(v01, 0.f);
                v10 = fmaxf(v10, 0.f);
                v11 = fmaxf(v11, 0.f);
            }
            if (Cf != nullptr) {
                ((float2*)(Cf + (size_t)row * N + col))[0]       = make_float2(v00, v01);
                ((float2*)(Cf + (size_t)(row + 8) * N + col))[0] = make_float2(v10, v11);
            }
            if (Chi != nullptr) {
                __nv_bfloat162 h0 = __floats2bfloat162_rn(v00, v01);
                __nv_bfloat162 h1 = __floats2bfloat162_rn(v10, v11);
                float l00 = v00 - __bfloat162float(__low2bfloat16(h0));
                float l01 = v01 - __bfloat162float(__high2bfloat16(h0));
                float l10 = v10 - __bfloat162float(__low2bfloat16(h1));
                float l11 = v11 - __bfloat162float(__high2bfloat16(h1));
                ((__nv_bfloat162*)(Chi + (size_t)row * N + col))[0]       = h0;
                ((__nv_bfloat162*)(Chi + (size_t)(row + 8) * N + col))[0] = h1;
                ((__nv_bfloat162*)(Clo + (size_t)row * N + col))[0]       = __floats2bfloat162_rn(l00, l01);
                ((__nv_bfloat162*)(Clo + (size_t)(row + 8) * N + col))[0] = __floats2bfloat162_rn(l10, l11);
            }
        }
    }
}

// ---------------- spatial-attention softmax + scale, emits xs as bf16 pair ----------------
__global__ void sa_softmax_kernel(const float* __restrict__ xb, const float* __restrict__ sx,
                                  __nv_bfloat16* __restrict__ oh, __nv_bfloat16* __restrict__ ol)
{
    int row = blockIdx.x;
    int f = threadIdx.x;
    size_t idx = ((size_t)row << 7) + f;
    float e = expf(sx[idx]);
    float sum = e;
#pragma unroll
    for (int o = 16; o > 0; o >>= 1) { sum += __shfl_xor_sync(0xffffffffu, sum, o); }
    __shared__ float red[4];
    if ((f & 31) == 0) { red[f >> 5] = sum; }
    __syncthreads();
    float tot = red[0] + red[1] + red[2] + red[3];
    float v = xb[idx] * e / tot;
    __nv_bfloat16 hi = __float2bfloat16(v);
    __nv_bfloat16 lo = __float2bfloat16(v - __bfloat162float(hi));
    oh[idx] = hi;
    ol[idx] = lo;
}

// ---------------- persistent LSTM layer (tensor-core recurrent GEMM, cluster barrier) ----
// Grid (16,8), cluster (16,1): one 16-CTA cluster per b-group (the exact sync domain —
// block (ux,by) writes h rows [by*32,by*32+32) and reads only those rows). Step sync is
// barrier.cluster arrive(release)/wait(acquire): replaces ATOMG+L2-spin+threadfence.
// Whh fragments are step-invariant and preloaded into registers (64/thread).
__global__ __launch_bounds__(256) __cluster_dims__(16, 1, 1) void lstm_persist_kernel(
    const float* __restrict__ G, const float* __restrict__ Whh,
    __nv_bfloat16* __restrict__ h16h, __nv_bfloat16* __restrict__ h16l,
    __nv_bfloat16* __restrict__ hallh, __nv_bfloat16* __restrict__ halll)
{
    extern __shared__ char dynsmem[];
    __nv_bfloat16* wsh = (__nv_bfloat16*)dynsmem;
    __nv_bfloat16* wsl = wsh + 64 * SROWK;
    __nv_bfloat16* hsh = wsl + 64 * SROWK;
    __nv_bfloat16* hsl = hsh + 32 * SROWK;
    float* Ssm = (float*)(hsl + 32 * SROWK);
    float* csm = Ssm + 32 * 68;

    const int u0 = blockIdx.x << 4;
    const int b0 = blockIdx.y << 5;
    const int tid = (int)threadIdx.x;
    const int wid = tid >> 5;
    const int lane = tid & 31;

    // one-time: convert Whh tile fp32 -> bf16 hi/lo in smem; zero c
#pragma unroll 4
    for (int i = 0; i < 16; i++) {
        int f4 = tid + (i << 8);
        int c  = f4 >> 6;
        int kq = (f4 & 63) << 2;
        int wrow = ((c >> 4) << 8) + u0 + (c & 15);
        float4 v = ((const float4*)(Whh + (size_t)wrow * Hn + kq))[0];
        __nv_bfloat162 h0 = __floats2bfloat162_rn(v.x, v.y);
        __nv_bfloat162 h1 = __floats2bfloat162_rn(v.z, v.w);
        float lx = v.x - __bfloat162float(__low2bfloat16(h0));
        float ly = v.y - __bfloat162float(__high2bfloat16(h0));
        float lz = v.z - __bfloat162float(__low2bfloat16(h1));
        float lw = v.w - __bfloat162float(__high2bfloat16(h1));
        ((__nv_bfloat162*)(wsh + c * SROWK + kq))[0] = h0;
        ((__nv_bfloat162*)(wsh + c * SROWK + kq))[1] = h1;
        ((__nv_bfloat162*)(wsl + c * SROWK + kq))[0] = __floats2bfloat162_rn(lx, ly);
        ((__nv_bfloat162*)(wsl + c * SROWK + kq))[1] = __floats2bfloat162_rn(lz, lw);
    }
    for (int i = tid; i < 32 * 18; i += 256) { csm[i] = 0.f; }
    __syncthreads();

    const int lane15 = lane & 15;
    const uint32_t aBaseH = (uint32_t)__cvta_generic_to_shared(hsh)
                          + (uint32_t)((lane15 * SROWK + ((lane >> 4) << 3)) * 2);
    const uint32_t aBaseL = (uint32_t)__cvta_generic_to_shared(hsl)
                          + (uint32_t)((lane15 * SROWK + ((lane >> 4) << 3)) * 2);
    const uint32_t bBaseH = (uint32_t)__cvta_generic_to_shared(wsh)
                          + (uint32_t)((((wid << 3) + (lane15 & 7)) * SROWK + (((lane15 >> 3) & 1) << 3)) * 2);
    const uint32_t bBaseL = (uint32_t)__cvta_generic_to_shared(wsl)
                          + (uint32_t)((((wid << 3) + (lane15 & 7)) * SROWK + (((lane15 >> 3) & 1) << 3)) * 2);

    // preload step-invariant Whh fragments into registers (this warp's n-strip)
    uint32_t wfh[16][2];
    uint32_t wfl[16][2];
#pragma unroll
    for (int ks = 0; ks < 16; ks++) {
        ldsm_x2(wfh[ks], bBaseH + (uint32_t)(ks * 32));
        ldsm_x2(wfl[ks], bBaseL + (uint32_t)(ks * 32));
    }

    const int uu = (tid << 1) & 15;
    const int bb = tid >> 3;
    const int gb = b0 + bb;
    const int gu = u0 + uu;

    for (int t = 0; t < Tn; t++) {
        // wait for previous step's h (cluster-wide acquire)
        if (t > 0) {
            asm volatile("barrier.cluster.wait.aligned;" ::: "memory");
        }

        // prefetch gate preactivations (DRAM latency hidden under staging+MMA)
        float2 gqi, gqf, gqg, gqo;
        {
            const float* gp = G + (((size_t)gb * Tn + t) << 10) + gu;
            gqi = ((const float2*)(gp +   0))[0];
            gqf = ((const float2*)(gp + 256))[0];
            gqg = ((const float2*)(gp + 512))[0];
            gqo = ((const float2*)(gp + 768))[0];
        }

        float acc0[4];
        float acc1[4];
#pragma unroll
        for (int j = 0; j < 4; j++) { acc0[j] = 0.f; acc1[j] = 0.f; }

        if (t > 0) {
            const __nv_bfloat16* hph = h16h + (size_t)(t & 1) * BH;
            const __nv_bfloat16* hpl = h16l + (size_t)(t & 1) * BH;
#pragma unroll 4
            for (int i = 0; i < 4; i++) {
                int f4 = tid + (i << 8);
                int hbb = f4 >> 5;
                int k8 = (f4 & 31) << 3;
                uint4 vh = __ldcg((const uint4*)(hph + (size_t)(b0 + hbb) * Hn + k8));
                uint4 vl = __ldcg((const uint4*)(hpl + (size_t)(b0 + hbb) * Hn + k8));
                ((uint4*)(hsh + hbb * SROWK + k8))[0] = vh;
                ((uint4*)(hsl + hbb * SROWK + k8))[0] = vl;
            }
            __syncthreads();

#pragma unroll
            for (int ks = 0; ks < 16; ks++) {
                const uint32_t koff = (uint32_t)(ks * 32);
                uint32_t a0[4];
                uint32_t a1[4];
                ldsm_x4(a0, aBaseH + koff);
                ldsm_x4(a1, aBaseH + (uint32_t)(16 * SROWK * 2) + koff);
                mma_bf16(acc0, a0, wfh[ks]);
                mma_bf16(acc1, a1, wfh[ks]);
                mma_bf16(acc0, a0, wfl[ks]);
                mma_bf16(acc1, a1, wfl[ks]);
                ldsm_x4(a0, aBaseL + koff);
                ldsm_x4(a1, aBaseL + (uint32_t)(16 * SROWK * 2) + koff);
                mma_bf16(acc0, a0, wfh[ks]);
                mma_bf16(acc1, a1, wfh[ks]);
            }
            // no __syncthreads needed: hsh/hsl are not rewritten until after the next
            // cluster wait + the __syncthreads following Ssm deposit below.
        }

        {
            int r0 = lane >> 2;
            int cb = (wid << 3) + ((lane & 3) << 1);
            Ssm[(r0 +  0) * 68 + cb]     = acc0[0];
            Ssm[(r0 +  0) * 68 + cb + 1] = acc0[1];
            Ssm[(r0 +  8) * 68 + cb]     = acc0[2];
            Ssm[(r0 +  8) * 68 + cb + 1] = acc0[3];
            Ssm[(r0 + 16) * 68 + cb]     = acc1[0];
            Ssm[(r0 + 16) * 68 + cb + 1] = acc1[1];
            Ssm[(r0 + 24) * 68 + cb]     = acc1[2];
            Ssm[(r0 + 24) * 68 + cb + 1] = acc1[3];
        }
        __syncthreads();

        {
            const float* S0 = Ssm + bb * 68;
            float hv[2];
            float cn[2];
            float2 cpv = ((const float2*)&csm[bb * 18 + uu])[0];
            float cprev[2] = {cpv.x, cpv.y};
            float gi2[2] = {gqi.x, gqi.y};
            float gf2[2] = {gqf.x, gqf.y};
            float gg2[2] = {gqg.x, gqg.y};
            float go2[2] = {gqo.x, gqo.y};
#pragma unroll
            for (int e = 0; e < 2; e++) {
                int ue = uu + e;
                float gi = gi2[e] + S0[ 0 + ue];
                float gf = gf2[e] + S0[16 + ue];
                float gg = gg2[e] + S0[32 + ue];
                float go = go2[e] + S0[48 + ue];
                float si = 1.f / (1.f + expf(-gi));
                float sf = 1.f / (1.f + expf(-gf));
                float so = 1.f / (1.f + expf(-go));
                float tg = tanhf(gg);
                cn[e] = sf * cprev[e] + si * tg;
                hv[e] = so * tanhf(cn[e]);
            }
            ((float2*)&csm[bb * 18 + uu])[0] = make_float2(cn[0], cn[1]);
            __nv_bfloat162 hh = __floats2bfloat162_rn(hv[0], hv[1]);
            float l0 = hv[0] - __bfloat162float(__low2bfloat16(hh));
            float l1 = hv[1] - __bfloat162float(__high2bfloat16(hh));
            __nv_bfloat162 hl = __floats2bfloat162_rn(l0, l1);
            size_t hoff = (size_t)((t + 1) & 1) * BH + (size_t)gb * Hn + gu;
            ((__nv_bfloat162*)(h16h + hoff))[0] = hh;
            ((__nv_bfloat162*)(h16l + hoff))[0] = hl;
            size_t aoff = ((size_t)gb * Tn + t) * Hn + gu;
            ((__nv_bfloat162*)(hallh + aoff))[0] = hh;
            ((__nv_bfloat162*)(halll + aoff))[0] = hl;
        }

        // release this step's h to the cluster (paired wait at next iteration's top)
        if (t < Tn - 1) {
            asm volatile("barrier.cluster.arrive.aligned;" ::: "memory");
        }
    }
}

// ---------------- temporal attention ----------------
__global__ void ctx_kernel(const float* __restrict__ blg, const float* __restrict__ tot,
                           float* __restrict__ ctx)
{
    int gid = blockIdx.x * 256 + threadIdx.x;
    int b = gid >> 7;
    int f = gid & 127;
    const float* lp = blg + (((size_t)b * Tn) << 7) + f;
    const float* tp = tot + (((size_t)b * Tn) << 7) + f;
    float m = -1e30f;
    for (int t = 0; t < Tn; t++) { m = fmaxf(m, lp[(size_t)t << 7]); }
    float s = 0.f;
    float w = 0.f;
    for (int t = 0; t < Tn; t++) {
        float e = expf(lp[(size_t)t << 7] - m);
        s += e;
        w = fmaf(e, tp[(size_t)t << 7], w);
    }
    ctx[gid] = w / s;
}

// ---------------- final projection ----------------
__global__ void out_kernel(const float* __restrict__ ctx, const float* __restrict__ ow,
                           float* __restrict__ out)
{
    int b = blockIdx.x;
    int f = threadIdx.x;
    float v = ctx[(b << 7) + f] * ow[f];
#pragma unroll
    for (int o = 16; o > 0; o >>= 1) { v += __shfl_xor_sync(0xffffffffu, v, o); }
    __shared__ float red[4];
    if ((f & 31) == 0) { red[f >> 5] = v; }
    __syncthreads();
    if (f == 0) { out[b] = red[0] + red[1] + red[2] + red[3]; }
}

// ---------------- host ----------------
extern "C" void kernel_launch(void* const* d_in, const int* in_sizes, int n_in,
                              void* d_out, int out_size)
{
    (void)in_sizes; (void)n_in; (void)out_size;
    const float* x    = (const float*)d_in[0];
    const float* bng  = (const float*)d_in[1];
    const float* bnb  = (const float*)d_in[2];
    const float* bnm  = (const float*)d_in[3];
    const float* bnv  = (const float*)d_in[4];
    const float* saW  = (const float*)d_in[5];
    const float* sab  = (const float*)d_in[6];
    const float* inW  = (const float*)d_in[7];
    const float* inb  = (const float*)d_in[8];
    const float* Wih0 = (const float*)d_in[9];
    const float* Whh0 = (const float*)d_in[10];
    const float* bih0 = (const float*)d_in[11];
    const float* bhh0 = (const float*)d_in[12];
    const float* Wih1 = (const float*)d_in[13];
    const float* Whh1 = (const float*)d_in[14];
    const float* bih1 = (const float*)d_in[15];
    const float* bhh1 = (const float*)d_in[16];
    const float* tahW = (const float*)d_in[17];
    const float* tahb = (const float*)d_in[18];
    const float* taW  = (const float*)d_in[19];
    const float* tab  = (const float*)d_in[20];
    const float* outW = (const float*)d_in[21];

    float *pF1, *pF2, *pG, *pCtx;
    __nv_bfloat16 *pAh, *pAl, *pBh, *pBl, *pWh, *pWl, *pHh, *pHl;
    cudaGetSymbolAddress((void**)&pF1, g_bufF1);
    cudaGetSymbolAddress((void**)&pF2, g_bufF2);
    cudaGetSymbolAddress((void**)&pG,  g_bufG);
    cudaGetSymbolAddress((void**)&pCtx, g_ctxbuf);
    cudaGetSymbolAddress((void**)&pAh, g_a16h);
    cudaGetSymbolAddress((void**)&pAl, g_a16l);
    cudaGetSymbolAddress((void**)&pBh, g_b16h);
    cudaGetSymbolAddress((void**)&pBl, g_b16l);
    cudaGetSymbolAddress((void**)&pWh, g_w16h);
    cudaGetSymbolAddress((void**)&pWl, g_w16l);
    cudaGetSymbolAddress((void**)&pHh, g_h16h);
    cudaGetSymbolAddress((void**)&pHl, g_h16l);

    const int lstm_smem = (64 * SROWK + 64 * SROWK + 32 * SROWK + 32 * SROWK) * 2
                        + (32 * 68 + 32 * 18) * 4;
    cudaFuncSetAttribute(lstm_persist_kernel,
                         cudaFuncAttributeMaxDynamicSharedMemorySize, lstm_smem);
    cudaFuncSetAttribute(lstm_persist_kernel,
                         cudaFuncAttributeNonPortableClusterSizeAllowed, 1);
    const int bf16_smem = 4 * 128 * SROW * 2;
    cudaFuncSetAttribute(gemm_bf16_kernel,
                         cudaFuncAttributeMaxDynamicSharedMemorySize, bf16_smem);

    // 1) BN: xb -> F1 fp32 + pair A1
    bn_kernel<<<(BT * Fn / 4) / 256, 256>>>((const float4*)x, (const float4*)bng,
        (const float4*)bnb, (const float4*)bnm, (const float4*)bnv, (float4*)pF1,
        (__nv_bfloat162*)pAh, (__nv_bfloat162*)pAl);

    // weight splits
    split_kernel<<<(Fn * Fn / 4) / 256, 256>>>((const float4*)saW,
        (__nv_bfloat162*)(pWh + W_SA), (__nv_bfloat162*)(pWl + W_SA));
    split_kernel<<<(Hn * Fn / 4) / 256, 256>>>((const float4*)inW,
        (__nv_bfloat162*)(pWh + W_IN), (__nv_bfloat162*)(pWl + W_IN));
    split_kernel<<<(4 * Hn * Hn / 4) / 256, 256>>>((const float4*)Wih0,
        (__nv_bfloat162*)(pWh + W_IH0), (__nv_bfloat162*)(pWl + W_IH0));
    split_kernel<<<(4 * Hn * Hn / 4) / 256, 256>>>((const float4*)Wih1,
        (__nv_bfloat162*)(pWh + W_IH1), (__nv_bfloat162*)(pWl + W_IH1));
    split_kernel<<<(Fn * Hn / 4) / 256, 256>>>((const float4*)tahW,
        (__nv_bfloat162*)(pWh + W_TAH), (__nv_bfloat162*)(pWl + W_TAH));
    split_kernel<<<(Fn * Fn / 4) / 256, 256>>>((const float4*)taW,
        (__nv_bfloat162*)(pWh + W_TA), (__nv_bfloat162*)(pWl + W_TA));

    // 2) SA logits
    gemm_bf16_kernel<<<dim3(1, BT / 128), 256, bf16_smem>>>(
        pAh, pAl, pWh + W_SA, pWl + W_SA, sab, nullptr, pF2, nullptr, nullptr, Fn, Fn, 1);

    // 3) softmax + scale -> xs pair A2
    sa_softmax_kernel<<<BT, 128>>>(pF1, pF2, pBh, pBl);

    // 4) layer_in -> h_in pair A1
    gemm_bf16_kernel<<<dim3(2, BT / 128), 256, bf16_smem>>>(
        pBh, pBl, pWh + W_IN, pWl + W_IN, inb, nullptr, nullptr, pAh, pAl, Hn, Fn, 0);

    // 5) LSTM layer 0
    gemm_bf16_kernel<<<dim3(8, BT / 128), 256, bf16_smem>>>(
        pAh, pAl, pWh + W_IH0, pWl + W_IH0, bih0, bhh0, pG, nullptr, nullptr, 4 * Hn, Hn, 0);
    lstm_persist_kernel<<<dim3(16, 8), 256, lstm_smem>>>(pG, Whh0, pHh, pHl, pBh, pBl);

    // 6) LSTM layer 1
    gemm_bf16_kernel<<<dim3(8, BT / 128), 256, bf16_smem>>>(
        pBh, pBl, pWh + W_IH1, pWl + W_IH1, bih1, bhh1, pG, nullptr, nullptr, 4 * Hn, Hn, 0);
    lstm_persist_kernel<<<dim3(16, 8), 256, lstm_smem>>>(pG, Whh1, pHh, pHl, pAh, pAl);

    // 7) temporal attention
    gemm_bf16_kernel<<<dim3(1, BT / 128), 256, bf16_smem>>>(
        pAh, pAl, pWh + W_TAH, pWl + W_TAH, tahb, nullptr, pF1, pBh, pBl, Fn, Hn, 0);
    gemm_bf16_kernel<<<dim3(1, BT / 128), 256, bf16_smem>>>(
        pBh, pBl, pWh + W_TA, pWl + W_TA, tab, nullptr, pF2, nullptr, nullptr, Fn, Fn, 2);
    ctx_kernel<<<(Bn * Fn) / 256, 256>>>(pF2, pF1, pCtx);

    // 8) output
    out_kernel<<<Bn, 128>>>(pCtx, outW, (float*)d_out);
}

// round 17
// speedup vs baseline: 1.2177x; 1.2177x over previous
#include <cuda_runtime.h>
#include <cuda_bf16.h>
#include <cstdint>

#define Bn 256
#define Tn 512
#define Fn 128
#define Hn 256
#define BT (Bn*Tn)
#define BH (Bn*Hn)
#define SROW 72
#define SROWK 264   // LSTM smem row stride (256 k + 8 pad)

// weight split buffer offsets (elements)
#define W_SA   0
#define W_IN   16384
#define W_IH0  49152
#define W_IH1  311296
#define W_TAH  573440
#define W_TA   606208
#define W_TOT  622592

// ---------------- scratch (device globals) ----------------
__device__ float g_bufF1[(size_t)BT * Fn];
__device__ float g_bufF2[(size_t)BT * Fn];
__device__ float g_bufG [(size_t)BT * 4 * Hn];
__device__ float g_ctxbuf[Bn * Fn];
__device__ unsigned g_bars[8 * 32];                 // per-b-group barrier counters (128B apart)
__device__ __nv_bfloat16 g_a16h[(size_t)BT * Hn];   // activation pair buffer A1
__device__ __nv_bfloat16 g_a16l[(size_t)BT * Hn];
__device__ __nv_bfloat16 g_b16h[(size_t)BT * Hn];   // activation pair buffer A2
__device__ __nv_bfloat16 g_b16l[(size_t)BT * Hn];
__device__ __nv_bfloat16 g_w16h[W_TOT];             // all weights hi
__device__ __nv_bfloat16 g_w16l[W_TOT];             // all weights lo
__device__ __nv_bfloat16 g_h16h[2 * BH];            // ping-pong h (bf16 hi)
__device__ __nv_bfloat16 g_h16l[2 * BH];            // ping-pong h (bf16 lo)

// ---------------- BatchNorm (eval) + bf16 pair emit ----------------
__global__ void bn_kernel(const float4* __restrict__ x, const float4* __restrict__ g,
                          const float4* __restrict__ bt, const float4* __restrict__ mn,
                          const float4* __restrict__ vr, float4* __restrict__ out,
                          __nv_bfloat162* __restrict__ oh, __nv_bfloat162* __restrict__ ol)
{
    int i = blockIdx.x * 256 + threadIdx.x;
    int fi = i & 31;
    float4 xv = x[i];
    float4 gv = g[fi];
    float4 bv = bt[fi];
    float4 mv = mn[fi];
    float4 vv = vr[fi];
    float4 r;
    r.x = (xv.x - mv.x) * rsqrtf(vv.x + 1e-5f) * gv.x + bv.x;
    r.y = (xv.y - mv.y) * rsqrtf(vv.y + 1e-5f) * gv.y + bv.y;
    r.z = (xv.z - mv.z) * rsqrtf(vv.z + 1e-5f) * gv.z + bv.z;
    r.w = (xv.w - mv.w) * rsqrtf(vv.w + 1e-5f) * gv.w + bv.w;
    out[i] = r;
    __nv_bfloat162 h0 = __floats2bfloat162_rn(r.x, r.y);
    __nv_bfloat162 h1 = __floats2bfloat162_rn(r.z, r.w);
    float lx = r.x - __bfloat162float(__low2bfloat16(h0));
    float ly = r.y - __bfloat162float(__high2bfloat16(h0));
    float lz = r.z - __bfloat162float(__low2bfloat16(h1));
    float lw = r.w - __bfloat162float(__high2bfloat16(h1));
    oh[2 * i]     = h0;
    oh[2 * i + 1] = h1;
    ol[2 * i]     = __floats2bfloat162_rn(lx, ly);
    ol[2 * i + 1] = __floats2bfloat162_rn(lz, lw);
}

// ---------------- fp32 -> bf16 hi/lo split (weights) ----------------
__global__ void split_kernel(const float4* __restrict__ x,
                             __nv_bfloat162* __restrict__ hh,
                             __nv_bfloat162* __restrict__ ll)
{
    int i = blockIdx.x * 256 + threadIdx.x;
    float4 v = x[i];
    __nv_bfloat162 h0 = __floats2bfloat162_rn(v.x, v.y);
    __nv_bfloat162 h1 = __floats2bfloat162_rn(v.z, v.w);
    float lx = v.x - __bfloat162float(__low2bfloat16(h0));
    float ly = v.y - __bfloat162float(__high2bfloat16(h0));
    float lz = v.z - __bfloat162float(__low2bfloat16(h1));
    float lw = v.w - __bfloat162float(__high2bfloat16(h1));
    hh[2 * i]     = h0;
    hh[2 * i + 1] = h1;
    ll[2 * i]     = __floats2bfloat162_rn(lx, ly);
    ll[2 * i + 1] = __floats2bfloat162_rn(lz, lw);
}

// ---------------- tensor-core helpers ----------------
__device__ __forceinline__ void ldsm_x4(uint32_t* r, uint32_t saddr)
{
    asm volatile("ldmatrix.sync.aligned.m8n8.x4.shared.b16 {%0,%1,%2,%3}, [%4];"
                 : "=r"(r[0]), "=r"(r[1]), "=r"(r[2]), "=r"(r[3]) : "r"(saddr));
}

__device__ __forceinline__ void ldsm_x2(uint32_t* r, uint32_t saddr)
{
    asm volatile("ldmatrix.sync.aligned.m8n8.x2.shared.b16 {%0,%1}, [%2];"
                 : "=r"(r[0]), "=r"(r[1]) : "r"(saddr));
}

__device__ __forceinline__ void mma_bf16(float* d, const uint32_t* a, const uint32_t* b)
{
    asm volatile("mma.sync.aligned.m16n8k16.row.col.f32.bf16.bf16.f32 "
                 "{%0,%1,%2,%3}, {%4,%5,%6,%7}, {%8,%9}, {%0,%1,%2,%3};"
                 : "+f"(d[0]), "+f"(d[1]), "+f"(d[2]), "+f"(d[3])
                 : "r"(a[0]), "r"(a[1]), "r"(a[2]), "r"(a[3]), "r"(b[0]), "r"(b[1]));
}

// ---------------- unified bf16-split tensor GEMM ----------------
__global__ __launch_bounds__(256) void gemm_bf16_kernel(
    const __nv_bfloat16* __restrict__ Ahg, const __nv_bfloat16* __restrict__ Alg,
    const __nv_bfloat16* __restrict__ Whg, const __nv_bfloat16* __restrict__ Wlg,
    const float* __restrict__ b1, const float* __restrict__ b2,
    float* __restrict__ Cf, __nv_bfloat16* __restrict__ Chi, __nv_bfloat16* __restrict__ Clo,
    int N, int K, int epi)
{
    extern __shared__ char dynsmem[];
    __nv_bfloat16* sAh = (__nv_bfloat16*)dynsmem;
    __nv_bfloat16* sAl = sAh + 128 * SROW;
    __nv_bfloat16* sWh = sAl + 128 * SROW;
    __nv_bfloat16* sWl = sWh + 128 * SROW;

    const int m0 = blockIdx.y << 7;
    const int n0 = blockIdx.x << 7;
    const int tid = (int)threadIdx.x;
    const int wid = tid >> 5;
    const int lane = tid & 31;
    const int wm0 = (wid >> 2) << 6;
    const int wn0 = (wid & 3) << 5;

    const int arow = (lane & 7) + (((lane >> 3) & 1) << 3);
    const int acol = (lane >> 4) << 3;
    const int brow = (lane & 7) + ((lane >> 4) << 3);
    const int bcol = ((lane >> 3) & 1) << 3;

    const uint32_t sAh0 = (uint32_t)__cvta_generic_to_shared(sAh) + (uint32_t)(((wm0 + arow) * SROW + acol) * 2);
    const uint32_t sAl0 = (uint32_t)__cvta_generic_to_shared(sAl) + (uint32_t)(((wm0 + arow) * SROW + acol) * 2);
    const uint32_t sWh0 = (uint32_t)__cvta_generic_to_shared(sWh) + (uint32_t)(((wn0 + brow) * SROW + bcol) * 2);
    const uint32_t sWl0 = (uint32_t)__cvta_generic_to_shared(sWl) + (uint32_t)(((wn0 + brow) * SROW + bcol) * 2);

    float acc[16][4];
#pragma unroll
    for (int i = 0; i < 16; i++) {
#pragma unroll
        for (int j = 0; j < 4; j++) { acc[i][j] = 0.f; }
    }

    const int lr = tid >> 1;
    const int lc = (tid & 1) << 5;
    const int nkc = K >> 6;

    for (int kc = 0; kc < nkc; kc++) {
        const __nv_bfloat16* ag = Ahg + (size_t)(m0 + lr) * K + kc * 64 + lc;
        const __nv_bfloat16* al = Alg + (size_t)(m0 + lr) * K + kc * 64 + lc;
        const __nv_bfloat16* wg = Whg + (size_t)(n0 + lr) * K + kc * 64 + lc;
        const __nv_bfloat16* wl = Wlg + (size_t)(n0 + lr) * K + kc * 64 + lc;
        __nv_bfloat16* dA_h = sAh + lr * SROW + lc;
        __nv_bfloat16* dA_l = sAl + lr * SROW + lc;
        __nv_bfloat16* dW_h = sWh + lr * SROW + lc;
        __nv_bfloat16* dW_l = sWl + lr * SROW + lc;
#pragma unroll
        for (int q = 0; q < 4; q++) {
            ((uint4*)(dA_h + q * 8))[0] = ((const uint4*)(ag + q * 8))[0];
            ((uint4*)(dA_l + q * 8))[0] = ((const uint4*)(al + q * 8))[0];
            ((uint4*)(dW_h + q * 8))[0] = ((const uint4*)(wg + q * 8))[0];
            ((uint4*)(dW_l + q * 8))[0] = ((const uint4*)(wl + q * 8))[0];
        }
        __syncthreads();

#pragma unroll
        for (int ks = 0; ks < 4; ks++) {
            const uint32_t koff = (uint32_t)(ks * 32);
            uint32_t afr[4][4];
            uint32_t bh[4][2];
            uint32_t bl[4][2];
#pragma unroll
            for (int fp = 0; fp < 2; fp++) {
                uint32_t tmp[4];
                ldsm_x4(tmp, sWh0 + (uint32_t)(fp * 16 * SROW * 2) + koff);
                bh[2 * fp][0] = tmp[0];
                bh[2 * fp][1] = tmp[1];
                bh[2 * fp + 1][0] = tmp[2];
                bh[2 * fp + 1][1] = tmp[3];
                ldsm_x4(tmp, sWl0 + (uint32_t)(fp * 16 * SROW * 2) + koff);
                bl[2 * fp][0] = tmp[0];
                bl[2 * fp][1] = tmp[1];
                bl[2 * fp + 1][0] = tmp[2];
                bl[2 * fp + 1][1] = tmp[3];
            }
#pragma unroll
            for (int fm = 0; fm < 4; fm++) {
                ldsm_x4(afr[fm], sAh0 + (uint32_t)(fm * 16 * SROW * 2) + koff);
            }
#pragma unroll
            for (int fm = 0; fm < 4; fm++) {
#pragma unroll
                for (int fn = 0; fn < 4; fn++) {
                    mma_bf16(acc[fm * 4 + fn], afr[fm], bh[fn]);
                    mma_bf16(acc[fm * 4 + fn], afr[fm], bl[fn]);
                }
            }
#pragma unroll
            for (int fm = 0; fm < 4; fm++) {
                ldsm_x4(afr[fm], sAl0 + (uint32_t)(fm * 16 * SROW * 2) + koff);
            }
#pragma unroll
            for (int fm = 0; fm < 4; fm++) {
#pragma unroll
                for (int fn = 0; fn < 4; fn++) {
                    mma_bf16(acc[fm * 4 + fn], afr[fm], bh[fn]);
                }
            }
        }
        __syncthreads();
    }

#pragma unroll
    for (int fm = 0; fm < 4; fm++) {
#pragma unroll
        for (int fn = 0; fn < 4; fn++) {
            float* d = acc[fm * 4 + fn];
            int row = m0 + wm0 + fm * 16 + (lane >> 2);
            int col = n0 + wn0 + fn * 8 + ((lane & 3) << 1);
            float bv0 = b1[col];
            float bv1 = b1[col + 1];
            if (b2 != nullptr) {
                bv0 += b2[col];
                bv1 += b2[col + 1];
            }
            float v00 = d[0] + bv0;
            float v01 = d[1] + bv1;
            float v10 = d[2] + bv0;
            float v11 = d[3] + bv1;
            if (epi == 1) {
                v00 = 1.f / (1.f + expf(-v00));
                v01 = 1.f / (1.f + expf(-v01));
                v10 = 1.f / (1.f + expf(-v10));
                v11 = 1.f / (1.f + expf(-v11));
            } else if (epi == 2) {
                v00 = fmaxf(v00, 0.f);
                v01 = fmaxf(v01, 0.f);
                v10 = fmaxf(v10, 0.f);
                v11 = fmaxf(v11, 0.f);
            }
            if (Cf != nullptr) {
                ((float2*)(Cf + (size_t)row * N + col))[0]       = make_float2(v00, v01);
                ((float2*)(Cf + (size_t)(row + 8) * N + col))[0] = make_float2(v10, v11);
            }
            if (Chi != nullptr) {
                __nv_bfloat162 h0 = __floats2bfloat162_rn(v00, v01);
                __nv_bfloat162 h1 = __floats2bfloat162_rn(v10, v11);
                float l00 = v00 - __bfloat162float(__low2bfloat16(h0));
                float l01 = v01 - __bfloat162float(__high2bfloat16(h0));
                float l10 = v10 - __bfloat162float(__low2bfloat16(h1));
                float l11 = v11 - __bfloat162float(__high2bfloat16(h1));
                ((__nv_bfloat162*)(Chi + (size_t)row * N + col))[0]       = h0;
                ((__nv_bfloat162*)(Chi + (size_t)(row + 8) * N + col))[0] = h1;
                ((__nv_bfloat162*)(Clo + (size_t)row * N + col))[0]       = __floats2bfloat162_rn(l00, l01);
                ((__nv_bfloat162*)(Clo + (size_t)(row + 8) * N + col))[0] = __floats2bfloat162_rn(l10, l11);
            }
        }
    }
}

// ---------------- spatial-attention softmax + scale, emits xs as bf16 pair ----------------
__global__ void sa_softmax_kernel(const float* __restrict__ xb, const float* __restrict__ sx,
                                  __nv_bfloat16* __restrict__ oh, __nv_bfloat16* __restrict__ ol)
{
    int row = blockIdx.x;
    int f = threadIdx.x;
    size_t idx = ((size_t)row << 7) + f;
    float e = expf(sx[idx]);
    float sum = e;
#pragma unroll
    for (int o = 16; o > 0; o >>= 1) { sum += __shfl_xor_sync(0xffffffffu, sum, o); }
    __shared__ float red[4];
    if ((f & 31) == 0) { red[f >> 5] = sum; }
    __syncthreads();
    float tot = red[0] + red[1] + red[2] + red[3];
    float v = xb[idx] * e / tot;
    __nv_bfloat16 hi = __float2bfloat16(v);
    __nv_bfloat16 lo = __float2bfloat16(v - __bfloat162float(hi));
    oh[idx] = hi;
    ol[idx] = lo;
}

// ---------------- persistent LSTM layer (tensor-core recurrent GEMM) ----------------
// 128 blocks = (16 u-tiles x 8 b-groups), 256 threads. Per-b-group software barrier
// (proven fastest in R12; the R14 hardware-cluster barrier REGRESSED ~1us/step).
// Whh fragments are step-invariant and preloaded into registers (64/thread) — removes
// 32 LDSM/warp/step from the critical loop.
__global__ __launch_bounds__(256) void lstm_persist_kernel(
    const float* __restrict__ G, const float* __restrict__ Whh,
    __nv_bfloat16* __restrict__ h16h, __nv_bfloat16* __restrict__ h16l,
    __nv_bfloat16* __restrict__ hallh, __nv_bfloat16* __restrict__ halll)
{
    extern __shared__ char dynsmem[];
    __nv_bfloat16* wsh = (__nv_bfloat16*)dynsmem;
    __nv_bfloat16* wsl = wsh + 64 * SROWK;
    __nv_bfloat16* hsh = wsl + 64 * SROWK;
    __nv_bfloat16* hsl = hsh + 32 * SROWK;
    float* Ssm = (float*)(hsl + 32 * SROWK);
    float* csm = Ssm + 32 * 68;

    const int u0 = blockIdx.x << 4;
    const int b0 = blockIdx.y << 5;
    const int tid = (int)threadIdx.x;
    const int wid = tid >> 5;
    const int lane = tid & 31;
    unsigned* bar = &g_bars[blockIdx.y << 5];   // this b-group's counter (128B-separated)

    // one-time: convert Whh tile fp32 -> bf16 hi/lo in smem; zero c
#pragma unroll 4
    for (int i = 0; i < 16; i++) {
        int f4 = tid + (i << 8);
        int c  = f4 >> 6;
        int kq = (f4 & 63) << 2;
        int wrow = ((c >> 4) << 8) + u0 + (c & 15);
        float4 v = ((const float4*)(Whh + (size_t)wrow * Hn + kq))[0];
        __nv_bfloat162 h0 = __floats2bfloat162_rn(v.x, v.y);
        __nv_bfloat162 h1 = __floats2bfloat162_rn(v.z, v.w);
        float lx = v.x - __bfloat162float(__low2bfloat16(h0));
        float ly = v.y - __bfloat162float(__high2bfloat16(h0));
        float lz = v.z - __bfloat162float(__low2bfloat16(h1));
        float lw = v.w - __bfloat162float(__high2bfloat16(h1));
        ((__nv_bfloat162*)(wsh + c * SROWK + kq))[0] = h0;
        ((__nv_bfloat162*)(wsh + c * SROWK + kq))[1] = h1;
        ((__nv_bfloat162*)(wsl + c * SROWK + kq))[0] = __floats2bfloat162_rn(lx, ly);
        ((__nv_bfloat162*)(wsl + c * SROWK + kq))[1] = __floats2bfloat162_rn(lz, lw);
    }
    for (int i = tid; i < 32 * 18; i += 256) { csm[i] = 0.f; }
    __syncthreads();

    const int lane15 = lane & 15;
    const uint32_t aBaseH = (uint32_t)__cvta_generic_to_shared(hsh)
                          + (uint32_t)((lane15 * SROWK + ((lane >> 4) << 3)) * 2);
    const uint32_t aBaseL = (uint32_t)__cvta_generic_to_shared(hsl)
                          + (uint32_t)((lane15 * SROWK + ((lane >> 4) << 3)) * 2);
    const uint32_t bBaseH = (uint32_t)__cvta_generic_to_shared(wsh)
                          + (uint32_t)((((wid << 3) + (lane15 & 7)) * SROWK + (((lane15 >> 3) & 1) << 3)) * 2);
    const uint32_t bBaseL = (uint32_t)__cvta_generic_to_shared(wsl)
                          + (uint32_t)((((wid << 3) + (lane15 & 7)) * SROWK + (((lane15 >> 3) & 1) << 3)) * 2);

    // preload step-invariant Whh fragments into registers (this warp's n-strip)
    uint32_t wfh[16][2];
    uint32_t wfl[16][2];
#pragma unroll
    for (int ks = 0; ks < 16; ks++) {
        ldsm_x2(wfh[ks], bBaseH + (uint32_t)(ks * 32));
        ldsm_x2(wfl[ks], bBaseL + (uint32_t)(ks * 32));
    }

    const int uu = (tid << 1) & 15;
    const int bb = tid >> 3;
    const int gb = b0 + bb;
    const int gu = u0 + uu;

    unsigned target = 0;
    for (int t = 0; t < Tn; t++) {
        // prefetch gate preactivations (DRAM latency hidden under staging+MMA)
        float2 gqi, gqf, gqg, gqo;
        {
            const float* gp = G + (((size_t)gb * Tn + t) << 10) + gu;
            gqi = ((const float2*)(gp +   0))[0];
            gqf = ((const float2*)(gp + 256))[0];
            gqg = ((const float2*)(gp + 512))[0];
            gqo = ((const float2*)(gp + 768))[0];
        }

        float acc0[4];
        float acc1[4];
#pragma unroll
        for (int j = 0; j < 4; j++) { acc0[j] = 0.f; acc1[j] = 0.f; }

        if (t > 0) {
            const __nv_bfloat16* hph = h16h + (size_t)(t & 1) * BH;
            const __nv_bfloat16* hpl = h16l + (size_t)(t & 1) * BH;
#pragma unroll 4
            for (int i = 0; i < 4; i++) {
                int f4 = tid + (i << 8);
                int hbb = f4 >> 5;
                int k8 = (f4 & 31) << 3;
                uint4 vh = __ldcg((const uint4*)(hph + (size_t)(b0 + hbb) * Hn + k8));
                uint4 vl = __ldcg((const uint4*)(hpl + (size_t)(b0 + hbb) * Hn + k8));
                ((uint4*)(hsh + hbb * SROWK + k8))[0] = vh;
                ((uint4*)(hsl + hbb * SROWK + k8))[0] = vl;
            }
            __syncthreads();

#pragma unroll
            for (int ks = 0; ks < 16; ks++) {
                const uint32_t koff = (uint32_t)(ks * 32);
                uint32_t a0[4];
                uint32_t a1[4];
                ldsm_x4(a0, aBaseH + koff);
                ldsm_x4(a1, aBaseH + (uint32_t)(16 * SROWK * 2) + koff);
                mma_bf16(acc0, a0, wfh[ks]);
                mma_bf16(acc1, a1, wfh[ks]);
                mma_bf16(acc0, a0, wfl[ks]);
                mma_bf16(acc1, a1, wfl[ks]);
                ldsm_x4(a0, aBaseL + koff);
                ldsm_x4(a1, aBaseL + (uint32_t)(16 * SROWK * 2) + koff);
                mma_bf16(acc0, a0, wfh[ks]);
                mma_bf16(acc1, a1, wfh[ks]);
            }
            // no __syncthreads here — hsh/hsl are not rewritten until after the
            // group barrier below, whose trailing __syncthreads orders all MMA reads.
        }

        {
            int r0 = lane >> 2;
            int cb = (wid << 3) + ((lane & 3) << 1);
            Ssm[(r0 +  0) * 68 + cb]     = acc0[0];
            Ssm[(r0 +  0) * 68 + cb + 1] = acc0[1];
            Ssm[(r0 +  8) * 68 + cb]     = acc0[2];
            Ssm[(r0 +  8) * 68 + cb + 1] = acc0[3];
            Ssm[(r0 + 16) * 68 + cb]     = acc1[0];
            Ssm[(r0 + 16) * 68 + cb + 1] = acc1[1];
            Ssm[(r0 + 24) * 68 + cb]     = acc1[2];
            Ssm[(r0 + 24) * 68 + cb + 1] = acc1[3];
        }
        __syncthreads();

        {
            const float* S0 = Ssm + bb * 68;
            float hv[2];
            float cn[2];
            float2 cpv = ((const float2*)&csm[bb * 18 + uu])[0];
            float cprev[2] = {cpv.x, cpv.y};
            float gi2[2] = {gqi.x, gqi.y};
            float gf2[2] = {gqf.x, gqf.y};
            float gg2[2] = {gqg.x, gqg.y};
            float go2[2] = {gqo.x, gqo.y};
#pragma unroll
            for (int e = 0; e < 2; e++) {
                int ue = uu + e;
                float gi = gi2[e] + S0[ 0 + ue];
                float gf = gf2[e] + S0[16 + ue];
                float gg = gg2[e] + S0[32 + ue];
                float go = go2[e] + S0[48 + ue];
                float si = 1.f / (1.f + expf(-gi));
                float sf = 1.f / (1.f + expf(-gf));
                float so = 1.f / (1.f + expf(-go));
                float tg = tanhf(gg);
                cn[e] = sf * cprev[e] + si * tg;
                hv[e] = so * tanhf(cn[e]);
            }
            ((float2*)&csm[bb * 18 + uu])[0] = make_float2(cn[0], cn[1]);
            __nv_bfloat162 hh = __floats2bfloat162_rn(hv[0], hv[1]);
            float l0 = hv[0] - __bfloat162float(__low2bfloat16(hh));
            float l1 = hv[1] - __bfloat162float(__high2bfloat16(hh));
            __nv_bfloat162 hl = __floats2bfloat162_rn(l0, l1);
            size_t hoff = (size_t)((t + 1) & 1) * BH + (size_t)gb * Hn + gu;
            ((__nv_bfloat162*)(h16h + hoff))[0] = hh;
            ((__nv_bfloat162*)(h16l + hoff))[0] = hl;
            size_t aoff = ((size_t)gb * Tn + t) * Hn + gu;
            ((__nv_bfloat162*)(hallh + aoff))[0] = hh;
            ((__nv_bfloat162*)(halll + aoff))[0] = hl;
        }

        // per-b-group barrier: only the 16 blocks sharing blockIdx.y must agree
        __syncthreads();
        __threadfence();
        target += 16u;
        if (tid == 0) {
            atomicAdd(bar, 1u);
            while (*((volatile unsigned*)bar) < target) { }
        }
        __syncthreads();
    }
}

// ---------------- temporal attention ----------------
__global__ void ctx_kernel(const float* __restrict__ blg, const float* __restrict__ tot,
                           float* __restrict__ ctx)
{
    int gid = blockIdx.x * 256 + threadIdx.x;
    int b = gid >> 7;
    int f = gid & 127;
    const float* lp = blg + (((size_t)b * Tn) << 7) + f;
    const float* tp = tot + (((size_t)b * Tn) << 7) + f;
    float m = -1e30f;
    for (int t = 0; t < Tn; t++) { m = fmaxf(m, lp[(size_t)t << 7]); }
    float s = 0.f;
    float w = 0.f;
    for (int t = 0; t < Tn; t++) {
        float e = expf(lp[(size_t)t << 7] - m);
        s += e;
        w = fmaf(e, tp[(size_t)t << 7], w);
    }
    ctx[gid] = w / s;
}

// ---------------- final projection ----------------
__global__ void out_kernel(const float* __restrict__ ctx, const float* __restrict__ ow,
                           float* __restrict__ out)
{
    int b = blockIdx.x;
    int f = threadIdx.x;
    float v = ctx[(b << 7) + f] * ow[f];
#pragma unroll
    for (int o = 16; o > 0; o >>= 1) { v += __shfl_xor_sync(0xffffffffu, v, o); }
    __shared__ float red[4];
    if ((f & 31) == 0) { red[f >> 5] = v; }
    __syncthreads();
    if (f == 0) { out[b] = red[0] + red[1] + red[2] + red[3]; }
}

// ---------------- host ----------------
extern "C" void kernel_launch(void* const* d_in, const int* in_sizes, int n_in,
                              void* d_out, int out_size)
{
    (void)in_sizes; (void)n_in; (void)out_size;
    const float* x    = (const float*)d_in[0];
    const float* bng  = (const float*)d_in[1];
    const float* bnb  = (const float*)d_in[2];
    const float* bnm  = (const float*)d_in[3];
    const float* bnv  = (const float*)d_in[4];
    const float* saW  = (const float*)d_in[5];
    const float* sab  = (const float*)d_in[6];
    const float* inW  = (const float*)d_in[7];
    const float* inb  = (const float*)d_in[8];
    const float* Wih0 = (const float*)d_in[9];
    const float* Whh0 = (const float*)d_in[10];
    const float* bih0 = (const float*)d_in[11];
    const float* bhh0 = (const float*)d_in[12];
    const float* Wih1 = (const float*)d_in[13];
    const float* Whh1 = (const float*)d_in[14];
    const float* bih1 = (const float*)d_in[15];
    const float* bhh1 = (const float*)d_in[16];
    const float* tahW = (const float*)d_in[17];
    const float* tahb = (const float*)d_in[18];
    const float* taW  = (const float*)d_in[19];
    const float* tab  = (const float*)d_in[20];
    const float* outW = (const float*)d_in[21];

    float *pF1, *pF2, *pG, *pCtx;
    unsigned* pBar;
    __nv_bfloat16 *pAh, *pAl, *pBh, *pBl, *pWh, *pWl, *pHh, *pHl;
    cudaGetSymbolAddress((void**)&pF1, g_bufF1);
    cudaGetSymbolAddress((void**)&pF2, g_bufF2);
    cudaGetSymbolAddress((void**)&pG,  g_bufG);
    cudaGetSymbolAddress((void**)&pCtx, g_ctxbuf);
    cudaGetSymbolAddress((void**)&pBar, g_bars);
    cudaGetSymbolAddress((void**)&pAh, g_a16h);
    cudaGetSymbolAddress((void**)&pAl, g_a16l);
    cudaGetSymbolAddress((void**)&pBh, g_b16h);
    cudaGetSymbolAddress((void**)&pBl, g_b16l);
    cudaGetSymbolAddress((void**)&pWh, g_w16h);
    cudaGetSymbolAddress((void**)&pWl, g_w16l);
    cudaGetSymbolAddress((void**)&pHh, g_h16h);
    cudaGetSymbolAddress((void**)&pHl, g_h16l);

    const int lstm_smem = (64 * SROWK + 64 * SROWK + 32 * SROWK + 32 * SROWK) * 2
                        + (32 * 68 + 32 * 18) * 4;
    cudaFuncSetAttribute(lstm_persist_kernel,
                         cudaFuncAttributeMaxDynamicSharedMemorySize, lstm_smem);
    const int bf16_smem = 4 * 128 * SROW * 2;
    cudaFuncSetAttribute(gemm_bf16_kernel,
                         cudaFuncAttributeMaxDynamicSharedMemorySize, bf16_smem);

    // 1) BN: xb -> F1 fp32 + pair A1
    bn_kernel<<<(BT * Fn / 4) / 256, 256>>>((const float4*)x, (const float4*)bng,
        (const float4*)bnb, (const float4*)bnm, (const float4*)bnv, (float4*)pF1,
        (__nv_bfloat162*)pAh, (__nv_bfloat162*)pAl);

    // weight splits
    split_kernel<<<(Fn * Fn / 4) / 256, 256>>>((const float4*)saW,
        (__nv_bfloat162*)(pWh + W_SA), (__nv_bfloat162*)(pWl + W_SA));
    split_kernel<<<(Hn * Fn / 4) / 256, 256>>>((const float4*)inW,
        (__nv_bfloat162*)(pWh + W_IN), (__nv_bfloat162*)(pWl + W_IN));
    split_kernel<<<(4 * Hn * Hn / 4) / 256, 256>>>((const float4*)Wih0,
        (__nv_bfloat162*)(pWh + W_IH0), (__nv_bfloat162*)(pWl + W_IH0));
    split_kernel<<<(4 * Hn * Hn / 4) / 256, 256>>>((const float4*)Wih1,
        (__nv_bfloat162*)(pWh + W_IH1), (__nv_bfloat162*)(pWl + W_IH1));
    split_kernel<<<(Fn * Hn / 4) / 256, 256>>>((const float4*)tahW,
        (__nv_bfloat162*)(pWh + W_TAH), (__nv_bfloat162*)(pWl + W_TAH));
    split_kernel<<<(Fn * Fn / 4) / 256, 256>>>((const float4*)taW,
        (__nv_bfloat162*)(pWh + W_TA), (__nv_bfloat162*)(pWl + W_TA));

    // 2) SA logits
    gemm_bf16_kernel<<<dim3(1, BT / 128), 256, bf16_smem>>>(
        pAh, pAl, pWh + W_SA, pWl + W_SA, sab, nullptr, pF2, nullptr, nullptr, Fn, Fn, 1);

    // 3) softmax + scale -> xs pair A2
    sa_softmax_kernel<<<BT, 128>>>(pF1, pF2, pBh, pBl);

    // 4) layer_in -> h_in pair A1
    gemm_bf16_kernel<<<dim3(2, BT / 128), 256, bf16_smem>>>(
        pBh, pBl, pWh + W_IN, pWl + W_IN, inb, nullptr, nullptr, pAh, pAl, Hn, Fn, 0);

    // 5) LSTM layer 0
    gemm_bf16_kernel<<<dim3(8, BT / 128), 256, bf16_smem>>>(
        pAh, pAl, pWh + W_IH0, pWl + W_IH0, bih0, bhh0, pG, nullptr, nullptr, 4 * Hn, Hn, 0);
    cudaMemsetAsync(pBar, 0, 8 * 32 * sizeof(unsigned));
    lstm_persist_kernel<<<dim3(16, 8), 256, lstm_smem>>>(pG, Whh0, pHh, pHl, pBh, pBl);

    // 6) LSTM layer 1
    gemm_bf16_kernel<<<dim3(8, BT / 128), 256, bf16_smem>>>(
        pBh, pBl, pWh + W_IH1, pWl + W_IH1, bih1, bhh1, pG, nullptr, nullptr, 4 * Hn, Hn, 0);
    cudaMemsetAsync(pBar, 0, 8 * 32 * sizeof(unsigned));
    lstm_persist_kernel<<<dim3(16, 8), 256, lstm_smem>>>(pG, Whh1, pHh, pHl, pAh, pAl);

    // 7) temporal attention
    gemm_bf16_kernel<<<dim3(1, BT / 128), 256, bf16_smem>>>(
        pAh, pAl, pWh + W_TAH, pWl + W_TAH, tahb, nullptr, pF1, pBh, pBl, Fn, Hn, 0);
    gemm_bf16_kernel<<<dim3(1, BT / 128), 256, bf16_smem>>>(
        pBh, pBl, pWh + W_TA, pWl + W_TA, tab, nullptr, pF2, nullptr, nullptr, Fn, Fn, 2);
    ctx_kernel<<<(Bn * Fn) / 256, 256>>>(pF2, pF1, pCtx);

    // 8) output
    out_kernel<<<Bn, 128>>>(pCtx, outW, (float*)d_out);
}